// round 1
// baseline (speedup 1.0000x reference)
#include <cuda_runtime.h>
#include <math_constants.h>

#define N_TOK 32768   // B*T = 8*4096
#define DIM   128
#define KCB   1024
#define NCB   8
#define KT    32      // codewords per smem tile
#define TPB   32      // threads per block == tokens per block

__device__ float  g_residual[N_TOK * DIM];
__device__ float  g_cnorm[NCB * KCB];
__device__ int    g_codes[N_TOK * NCB];
__device__ double g_loss[NCB];

__global__ void zero_loss_kernel() {
    if (threadIdx.x < NCB) g_loss[threadIdx.x] = 0.0;
}

__global__ void cnorm_kernel(const float* __restrict__ cbs) {
    int idx = blockIdx.x * blockDim.x + threadIdx.x;
    if (idx >= NCB * KCB) return;
    const float4* v = (const float4*)(cbs + (size_t)idx * DIM);
    float4 a = make_float4(0.f, 0.f, 0.f, 0.f);
#pragma unroll
    for (int i = 0; i < DIM / 4; i++) {
        float4 x = v[i];
        a.x = fmaf(x.x, x.x, a.x);
        a.y = fmaf(x.y, x.y, a.y);
        a.z = fmaf(x.z, x.z, a.z);
        a.w = fmaf(x.w, x.w, a.w);
    }
    g_cnorm[idx] = (a.x + a.y) + (a.z + a.w);
}

__global__ void __launch_bounds__(TPB)
rvq_step_kernel(const float* __restrict__ emb,
                const float* __restrict__ cb,   // this codebook [K, D]
                int cb_idx, int use_emb) {
    __shared__ float s_cb[KT * DIM];
    __shared__ float s_cn[KT];

    const float* src = use_emb ? emb : (const float*)g_residual;
    const float* cn  = g_cnorm + (size_t)cb_idx * KCB;
    int n = blockIdx.x * TPB + threadIdx.x;

    float4 r[DIM / 4];
    const float4* sv = (const float4*)(src + (size_t)n * DIM);
#pragma unroll
    for (int i = 0; i < DIM / 4; i++) r[i] = sv[i];

    float4 a = make_float4(0.f, 0.f, 0.f, 0.f);
#pragma unroll
    for (int i = 0; i < DIM / 4; i++) {
        a.x = fmaf(r[i].x, r[i].x, a.x);
        a.y = fmaf(r[i].y, r[i].y, a.y);
        a.z = fmaf(r[i].z, r[i].z, a.z);
        a.w = fmaf(r[i].w, r[i].w, a.w);
    }
    float rn = (a.x + a.y) + (a.z + a.w);

    float bestd = CUDART_INF_F;
    int bestk = 0;

#pragma unroll 1
    for (int t0 = 0; t0 < KCB; t0 += KT) {
        __syncthreads();
        {
            const float4* g = (const float4*)(cb + (size_t)t0 * DIM);
            float4* s = (float4*)s_cb;
#pragma unroll
            for (int i = threadIdx.x; i < KT * DIM / 4; i += TPB) s[i] = g[i];
            if (threadIdx.x < KT) s_cn[threadIdx.x] = cn[t0 + threadIdx.x];
        }
        __syncthreads();

#pragma unroll 1
        for (int kk = 0; kk < KT; kk += 4) {
            const float4* c0 = (const float4*)(s_cb + (kk + 0) * DIM);
            const float4* c1 = (const float4*)(s_cb + (kk + 1) * DIM);
            const float4* c2 = (const float4*)(s_cb + (kk + 2) * DIM);
            const float4* c3 = (const float4*)(s_cb + (kk + 3) * DIM);
            float4 a0 = make_float4(0.f, 0.f, 0.f, 0.f);
            float4 a1 = make_float4(0.f, 0.f, 0.f, 0.f);
            float4 a2 = make_float4(0.f, 0.f, 0.f, 0.f);
            float4 a3 = make_float4(0.f, 0.f, 0.f, 0.f);
#pragma unroll
            for (int i = 0; i < DIM / 4; i++) {
                float4 ri = r[i];
                float4 x0 = c0[i];
                a0.x = fmaf(ri.x, x0.x, a0.x);
                a0.y = fmaf(ri.y, x0.y, a0.y);
                a0.z = fmaf(ri.z, x0.z, a0.z);
                a0.w = fmaf(ri.w, x0.w, a0.w);
                float4 x1 = c1[i];
                a1.x = fmaf(ri.x, x1.x, a1.x);
                a1.y = fmaf(ri.y, x1.y, a1.y);
                a1.z = fmaf(ri.z, x1.z, a1.z);
                a1.w = fmaf(ri.w, x1.w, a1.w);
                float4 x2 = c2[i];
                a2.x = fmaf(ri.x, x2.x, a2.x);
                a2.y = fmaf(ri.y, x2.y, a2.y);
                a2.z = fmaf(ri.z, x2.z, a2.z);
                a2.w = fmaf(ri.w, x2.w, a2.w);
                float4 x3 = c3[i];
                a3.x = fmaf(ri.x, x3.x, a3.x);
                a3.y = fmaf(ri.y, x3.y, a3.y);
                a3.z = fmaf(ri.z, x3.z, a3.z);
                a3.w = fmaf(ri.w, x3.w, a3.w);
            }
            float dot0 = (a0.x + a0.y) + (a0.z + a0.w);
            float dot1 = (a1.x + a1.y) + (a1.z + a1.w);
            float dot2 = (a2.x + a2.y) + (a2.z + a2.w);
            float dot3 = (a3.x + a3.y) + (a3.z + a3.w);
            float d0 = fmaf(-2.f, dot0, rn) + s_cn[kk + 0];
            float d1 = fmaf(-2.f, dot1, rn) + s_cn[kk + 1];
            float d2v = fmaf(-2.f, dot2, rn) + s_cn[kk + 2];
            float d3 = fmaf(-2.f, dot3, rn) + s_cn[kk + 3];
            if (d0 < bestd) { bestd = d0; bestk = t0 + kk + 0; }
            if (d1 < bestd) { bestd = d1; bestk = t0 + kk + 1; }
            if (d2v < bestd) { bestd = d2v; bestk = t0 + kk + 2; }
            if (d3 < bestd) { bestd = d3; bestk = t0 + kk + 3; }
        }
    }

    const float4* qv = (const float4*)(cb + (size_t)bestk * DIM);
    double lsum = 0.0;
#pragma unroll
    for (int i = 0; i < DIM / 4; i++) {
        float4 q = qv[i];
        r[i].x -= q.x; r[i].y -= q.y; r[i].z -= q.z; r[i].w -= q.w;
        lsum += (double)r[i].x * (double)r[i].x;
        lsum += (double)r[i].y * (double)r[i].y;
        lsum += (double)r[i].z * (double)r[i].z;
        lsum += (double)r[i].w * (double)r[i].w;
    }
    float4* rv = (float4*)(g_residual + (size_t)n * DIM);
#pragma unroll
    for (int i = 0; i < DIM / 4; i++) rv[i] = r[i];
    g_codes[n * NCB + cb_idx] = bestk;

#pragma unroll
    for (int off = 16; off; off >>= 1)
        lsum += __shfl_down_sync(0xFFFFFFFFu, lsum, off);
    if (threadIdx.x == 0) atomicAdd(&g_loss[cb_idx], lsum);
}

__global__ void finalize_kernel(const float* __restrict__ emb,
                                const float* __restrict__ cbs,
                                float* oc, float* oq, float* ol) {
    int n = blockIdx.x * blockDim.x + threadIdx.x;
    if (n >= N_TOK) return;

    float4 q[DIM / 4];
#pragma unroll
    for (int i = 0; i < DIM / 4; i++) q[i] = make_float4(0.f, 0.f, 0.f, 0.f);

#pragma unroll 1
    for (int c = 0; c < NCB; c++) {
        int k = g_codes[n * NCB + c];
        const float4* w = (const float4*)(cbs + ((size_t)c * KCB + k) * DIM);
#pragma unroll
        for (int i = 0; i < DIM / 4; i++) {
            float4 x = w[i];
            q[i].x += x.x; q[i].y += x.y; q[i].z += x.z; q[i].w += x.w;
        }
        if (oc) oc[n * NCB + c] = (float)k;
    }

    if (oq) {
        const float4* ev = (const float4*)(emb + (size_t)n * DIM);
        float4* ov = (float4*)(oq + (size_t)n * DIM);
#pragma unroll
        for (int i = 0; i < DIM / 4; i++) {
            float4 e = ev[i];
            float4 o;
            o.x = e.x + (q[i].x - e.x);
            o.y = e.y + (q[i].y - e.y);
            o.z = e.z + (q[i].z - e.z);
            o.w = e.w + (q[i].w - e.w);
            ov[i] = o;
        }
    }

    if (n == 0 && ol) {
        float l = 0.f;
#pragma unroll 1
        for (int c = 0; c < NCB; c++)
            l = l + (float)(g_loss[c] / (double)((size_t)N_TOK * DIM));
        *ol = l / (float)NCB;
    }
}

extern "C" void kernel_launch(void* const* d_in, const int* in_sizes, int n_in,
                              void* d_out, int out_size) {
    const float* emb = (const float*)d_in[0];  // embeddings [8,4096,128] f32
    const float* cbs = (const float*)d_in[1];  // codebooks  [8,1024,128] f32
    float* out = (float*)d_out;

    const long CODES_ELEMS = (long)N_TOK * NCB;        // 262144
    const long QUANT_ELEMS = (long)N_TOK * DIM;        // 4194304
    const long TOTAL = CODES_ELEMS + QUANT_ELEMS + 1;  // 4456449

    float *oc = nullptr, *oq = nullptr, *ol = nullptr;
    if ((long)out_size == TOTAL) {
        oc = out; oq = out + CODES_ELEMS; ol = out + CODES_ELEMS + QUANT_ELEMS;
    } else if ((long)out_size == QUANT_ELEMS) {
        oq = out;
    } else if ((long)out_size == CODES_ELEMS) {
        oc = out;
    } else if (out_size == 1) {
        ol = out;
    } else {
        oc = out;
        if ((long)out_size >= CODES_ELEMS + QUANT_ELEMS) oq = out + CODES_ELEMS;
        if ((long)out_size >= TOTAL) ol = out + CODES_ELEMS + QUANT_ELEMS;
    }

    zero_loss_kernel<<<1, 32>>>();
    cnorm_kernel<<<(NCB * KCB + 127) / 128, 128>>>(cbs);

    for (int c = 0; c < NCB; c++) {
        const float* cb = cbs + (size_t)c * KCB * DIM;
        rvq_step_kernel<<<N_TOK / TPB, TPB>>>(emb, cb, c, c == 0 ? 1 : 0);
    }

    finalize_kernel<<<(N_TOK + 127) / 128, 128>>>(emb, cbs, oc, oq, ol);
}